// round 2
// baseline (speedup 1.0000x reference)
#include <cuda_runtime.h>
#include <cuda_bf16.h>
#include <math.h>

// ---------------- problem constants ----------------
#define BB 64      // batch
#define SS 128     // seq len
#define LW 20      // chars per word
#define CE 30      // char emb
#define CC 30      // char conv channels
#define WE 300     // word emb
#define HH 256     // hidden
#define NCL 25     // num classes
#define FF 330     // feature = WE + CC
#define FP 336     // padded feature (multiple of 16)
#define NROW 8192  // S*B token rows
#define N2 2048    // 2 dirs * 4H

// ---------------- static device scratch ----------------
__device__ float g_feat[(size_t)NROW * FP];   // [s*64+b][FP]
__device__ float g_wpad[(size_t)N2 * FP];     // padded w_ih (fwd rows 0..1023, rev 1024..2047)
__device__ float g_gx[(size_t)NROW * N2];     // [(t*2048+col)*64 + b]
__device__ float g_hbuf[2 * 2 * HH * BB];     // [dir][parity][u][b]
__device__ float g_hseq[(size_t)NROW * 512];  // [(t*512+u)*64 + b]
__device__ float g_em[(size_t)NROW * NCL];    // [(t*64+b)*25 + c]
__device__ int   g_mask[BB * SS];             // [b][t]
__device__ float g_nll[BB];
__device__ unsigned g_bar;
__device__ volatile unsigned g_gen;

__device__ __forceinline__ float sigf(float x) { return 1.0f / (1.0f + __expf(-x)); }

// ---------------- init ----------------
__global__ void init_kernel() {
    int tid = blockIdx.x * blockDim.x + threadIdx.x;
    if (tid == 0) { g_bar = 0u; g_gen = 0u; }
    for (int i = tid; i < 2 * 2 * HH * BB; i += blockDim.x * gridDim.x) g_hbuf[i] = 0.0f;
    if (tid < BB) g_nll[tid] = 0.0f;
}

// ---------------- mask dtype detect + convert ----------------
__global__ void mask_convert_kernel(const unsigned* __restrict__ m) {
    unsigned v0 = m[0];
    int mode;  // 0 = int32, 1 = bytes, 2 = float32
    if (v0 == 0x01010101u) mode = 1;
    else if (v0 == 0x3F800000u) mode = 2;
    else mode = 0;
    int tid = blockIdx.x * blockDim.x + threadIdx.x;
    if (tid >= BB * SS) return;
    int v;
    if (mode == 1) {
        const unsigned char* mb = (const unsigned char*)m;
        v = (mb[tid] != 0) ? 1 : 0;
    } else if (mode == 2) {
        const float* mf = (const float*)m;
        v = (mf[tid] != 0.0f) ? 1 : 0;
    } else {
        v = (m[tid] != 0u) ? 1 : 0;
    }
    g_mask[tid] = v;
}

// ---------------- pad w_ih into [2048][336] ----------------
__global__ void pad_w_kernel(const float* __restrict__ w_ih_f,
                             const float* __restrict__ w_ih_r) {
    int idx = blockIdx.x * blockDim.x + threadIdx.x;
    if (idx >= N2 * FP) return;
    int r = idx / FP, k = idx - r * FP;
    float v = 0.0f;
    if (k < FF) v = (r < 1024) ? w_ih_f[r * FF + k] : w_ih_r[(r - 1024) * FF + k];
    g_wpad[idx] = v;
}

// ---------------- char CNN + embedding concat -> feat ----------------
__global__ __launch_bounds__(128) void embed_conv_kernel(
    const float* __restrict__ word_table, const float* __restrict__ char_table,
    const float* __restrict__ conv_w, const float* __restrict__ conv_b,
    const int* __restrict__ sent, const int* __restrict__ word) {
    int tok = blockIdx.x;          // tok = b*128 + s
    int b = tok >> 7, s = tok & 127;
    int row = s * BB + b;          // seq-major row
    int tid = threadIdx.x;

    __shared__ float wsm[CC * CE * 3];    // 2700
    __shared__ float psm[(LW + 2) * CE];  // padded char emb [pos][ic]
    __shared__ float csm[CC * LW];        // conv outputs [oc][t]

    for (int i = tid; i < CC * CE * 3; i += 128) wsm[i] = conv_w[i];
    for (int i = tid; i < (LW + 2) * CE; i += 128) psm[i] = 0.0f;
    __syncthreads();
    for (int i = tid; i < LW * CE; i += 128) {
        int l = i / CE, e = i - l * CE;
        int c = word[tok * LW + l];
        psm[(l + 1) * CE + e] = (c == 0) ? 0.0f : char_table[c * CE + e];
    }
    __syncthreads();
    for (int idx = tid; idx < CC * LW; idx += 128) {
        int oc = idx / LW, t = idx - oc * LW;
        const float* wr = wsm + oc * (CE * 3);
        float sum = 0.0f;
#pragma unroll
        for (int k = 0; k < 3; k++) {
            const float* xr = psm + (t + k) * CE;
#pragma unroll
            for (int ic = 0; ic < CE; ic++) sum += xr[ic] * wr[ic * 3 + k];
        }
        csm[oc * LW + t] = sum;
    }
    // word embedding copy (independent of csm)
    int widx = sent[tok];
    float* frow = g_feat + (size_t)row * FP;
    for (int i = tid; i < WE; i += 128) frow[i] = word_table[(size_t)widx * WE + i];
    __syncthreads();
    if (tid < CC) {
        float m = -1e30f;
#pragma unroll
        for (int t = 0; t < LW; t++) m = fmaxf(m, csm[tid * LW + t]);
        frow[WE + tid] = m + conv_b[tid];
    }
    if (tid >= CC && tid < CC + (FP - FF)) frow[WE + tid] = 0.0f;  // pad cols
}

// ---------------- gx GEMM: [8192 x 2048] = feat @ wpad^T ----------------
// output transposed per timestep: g_gx[(t*2048 + col)*64 + b]
__global__ __launch_bounds__(256) void gemm_gx_kernel(const float* __restrict__ bf,
                                                      const float* __restrict__ br) {
    __shared__ float As[16][64];
    __shared__ float Bs[16][64];
    int n0 = blockIdx.x * 64;
    int t = blockIdx.y;           // one timestep = 64 batch rows
    int m0 = t * 64;
    int tid = threadIdx.x;
    int tx = tid & 15, ty = tid >> 4;

    float acc[4][4];
#pragma unroll
    for (int i = 0; i < 4; i++)
#pragma unroll
        for (int j = 0; j < 4; j++) acc[i][j] = 0.0f;

    int lr = tid >> 2;            // 0..63
    int lk = (tid & 3) * 4;       // 0,4,8,12

    for (int k0 = 0; k0 < FP; k0 += 16) {
        float4 av = *(const float4*)&g_feat[(size_t)(m0 + lr) * FP + k0 + lk];
        float4 bv = *(const float4*)&g_wpad[(size_t)(n0 + lr) * FP + k0 + lk];
        __syncthreads();
        As[lk + 0][lr] = av.x; As[lk + 1][lr] = av.y; As[lk + 2][lr] = av.z; As[lk + 3][lr] = av.w;
        Bs[lk + 0][lr] = bv.x; Bs[lk + 1][lr] = bv.y; Bs[lk + 2][lr] = bv.z; Bs[lk + 3][lr] = bv.w;
        __syncthreads();
#pragma unroll
        for (int kk = 0; kk < 16; kk++) {
            float4 a  = *(const float4*)&As[kk][ty * 4];
            float4 b4 = *(const float4*)&Bs[kk][tx * 4];
            float ar[4]  = {a.x, a.y, a.z, a.w};
            float brg[4] = {b4.x, b4.y, b4.z, b4.w};
#pragma unroll
            for (int i = 0; i < 4; i++)
#pragma unroll
                for (int j = 0; j < 4; j++) acc[i][j] += ar[i] * brg[j];
        }
    }
#pragma unroll
    for (int j = 0; j < 4; j++) {
        int col = n0 + tx * 4 + j;
        float bias = (col < 1024) ? bf[col] : br[col - 1024];
#pragma unroll
        for (int i = 0; i < 4; i++) {
            int b = ty * 4 + i;
            g_gx[((size_t)t * N2 + col) * 64 + b] = acc[i][j] + bias;
        }
    }
}

// ---------------- grid barrier (128 co-resident blocks) ----------------
__device__ __forceinline__ void grid_barrier(unsigned nb) {
    __syncthreads();
    if (threadIdx.x == 0) {
        __threadfence();
        unsigned gen = g_gen;
        if (atomicAdd(&g_bar, 1u) == nb - 1u) {
            g_bar = 0u;
            __threadfence();
            g_gen = gen + 1u;
        } else {
            while (g_gen == gen) { __nanosleep(32); }
        }
    }
    __syncthreads();
}

// ---------------- persistent bidirectional LSTM ----------------
// 128 blocks: 0..63 forward, 64..127 reverse. Each block owns 4 hidden units
// (all 4 gates) x all 64 samples. Dynamic smem: W slice 16KB + h stage 64KB.
#define LSTM_SMEM ((16 * 256 + 256 * 64) * 4)
__global__ __launch_bounds__(256) void lstm_kernel(const float* __restrict__ whh_f,
                                                   const float* __restrict__ whh_r) {
    extern __shared__ float sm[];
    float* Wsm = sm;             // [(g*4+j)*256 + k]
    float* Hsm = sm + 16 * 256;  // [k*64 + b]

    int dir = blockIdx.x >> 6;
    int u0 = (blockIdx.x & 63) * 4;
    const float* whh = dir ? whh_r : whh_f;
    int tid = threadIdx.x;
    int b = tid & 63;
    int j = tid >> 6;            // unit within block, uniform per warp

    // load W_hh slice: rows {g*256 + u0 + jj}
    for (int i = tid; i < 16 * 256; i += 256) {
        int r = i >> 8, k = i & 255;
        int g = r >> 2, jj = r & 3;
        Wsm[r * 256 + k] = whh[(size_t)(g * 256 + u0 + jj) * 256 + k];
    }

    float c = 0.0f;
    int p = 0;

    for (int step = 0; step < 128; step++) {
        int t = dir ? (127 - step) : step;
        if (step > 0) grid_barrier(128u);

        // stage previous h [256][64] from global into smem
        {
            const float4* src = (const float4*)(g_hbuf + (dir * 2 + p) * (HH * BB));
            float4* dst = (float4*)Hsm;
            for (int i = tid; i < (HH * BB) / 4; i += 256) dst[i] = src[i];
        }
        __syncthreads();

        // gates init from gx
        size_t gxb = ((size_t)t * N2 + dir * 1024 + u0 + j) * 64 + b;
        float a0 = g_gx[gxb];                 // i
        float a1 = g_gx[gxb + 256 * 64];      // f
        float a2 = g_gx[gxb + 512 * 64];      // g
        float a3 = g_gx[gxb + 768 * 64];      // o

        const float* w0 = Wsm + (0 * 4 + j) * 256;
        const float* w1 = Wsm + (1 * 4 + j) * 256;
        const float* w2 = Wsm + (2 * 4 + j) * 256;
        const float* w3 = Wsm + (3 * 4 + j) * 256;

#pragma unroll 4
        for (int k = 0; k < 256; k += 4) {
            float hv0 = Hsm[(k + 0) * 64 + b];
            float hv1 = Hsm[(k + 1) * 64 + b];
            float hv2 = Hsm[(k + 2) * 64 + b];
            float hv3 = Hsm[(k + 3) * 64 + b];
            float4 q0 = *(const float4*)(w0 + k);
            float4 q1 = *(const float4*)(w1 + k);
            float4 q2 = *(const float4*)(w2 + k);
            float4 q3 = *(const float4*)(w3 + k);
            a0 += q0.x * hv0 + q0.y * hv1 + q0.z * hv2 + q0.w * hv3;
            a1 += q1.x * hv0 + q1.y * hv1 + q1.z * hv2 + q1.w * hv3;
            a2 += q2.x * hv0 + q2.y * hv1 + q2.z * hv2 + q2.w * hv3;
            a3 += q3.x * hv0 + q3.y * hv1 + q3.z * hv2 + q3.w * hv3;
        }

        float ig = sigf(a0), fg = sigf(a1), gg = tanhf(a2), og = sigf(a3);
        c = fg * c + ig * gg;
        float h = og * tanhf(c);

        int pn = p ^ 1;
        g_hbuf[((dir * 2 + pn) * HH + u0 + j) * 64 + b] = h;
        g_hseq[((size_t)t * 512 + dir * 256 + u0 + j) * 64 + b] = h;
        p = pn;
    }
}

// ---------------- emission: em = h @ lin_w^T + lin_b ----------------
__global__ __launch_bounds__(256) void emission_kernel(const float* __restrict__ lin_w,
                                                       const float* __restrict__ lin_b) {
    int t = blockIdx.x;
    int tid = threadIdx.x;
    int b = tid & 63;
    int cg = tid >> 6;  // 0..3

    float acc[7];
    int cs[7];
    int nc = 0;
    for (int ci = 0; ci < 7; ci++) {
        int cval = cg + 4 * ci;
        if (cval < NCL) { cs[nc] = cval; acc[nc] = lin_b[cval]; nc++; }
    }
    for (int u = 0; u < 512; u++) {
        float hv = g_hseq[((size_t)t * 512 + u) * 64 + b];
        for (int ci = 0; ci < nc; ci++) acc[ci] += hv * __ldg(&lin_w[cs[ci] * 512 + u]);
    }
    for (int ci = 0; ci < nc; ci++)
        g_em[((size_t)t * 64 + b) * NCL + cs[ci]] = acc[ci];
}

// ---------------- CRF NLL (one block per batch, 1 warp) ----------------
__global__ __launch_bounds__(32) void crf_kernel(const int* __restrict__ tag,
                                                 const float* __restrict__ start_t,
                                                 const float* __restrict__ end_t,
                                                 const float* __restrict__ trans) {
    int b = blockIdx.x;
    int lane = threadIdx.x;

    __shared__ float tr[NCL * NCL];
    __shared__ float alphas[32];

    for (int i = lane; i < NCL * NCL; i += 32) tr[i] = trans[i];
    __syncwarp();

    // gold-path score + length (parallel over t)
    float myscore = 0.0f;
    int mylen = 0;
    for (int t = lane; t < SS; t += 32) {
        int mk = g_mask[b * SS + t];
        mylen += mk;
        int tgt = tag[b * SS + t];
        if (t == 0) {
            myscore += start_t[tgt] + g_em[(size_t)b * NCL + tgt];
        } else if (mk) {
            int tgp = tag[b * SS + t - 1];
            myscore += tr[tgp * NCL + tgt] + g_em[((size_t)t * 64 + b) * NCL + tgt];
        }
    }
#pragma unroll
    for (int off = 16; off > 0; off >>= 1) {
        myscore += __shfl_xor_sync(0xFFFFFFFFu, myscore, off);
        mylen += __shfl_xor_sync(0xFFFFFFFFu, mylen, off);
    }
    float score = 0.0f;
    if (lane == 0) {
        int last = mylen - 1;
        score = myscore + end_t[tag[b * SS + last]];
    }

    // forward algorithm
    if (lane < NCL) alphas[lane] = start_t[lane] + g_em[(size_t)b * NCL + lane];
    __syncwarp();

    for (int t = 1; t < SS; t++) {
        int mk = g_mask[b * SS + t];
        float nxt = 0.0f;
        if (lane < NCL) {
            float emv = g_em[((size_t)t * 64 + b) * NCL + lane];
            float m = -1e30f;
#pragma unroll
            for (int i = 0; i < NCL; i++) m = fmaxf(m, alphas[i] + tr[i * NCL + lane]);
            float s = 0.0f;
#pragma unroll
            for (int i = 0; i < NCL; i++) s += __expf(alphas[i] + tr[i * NCL + lane] - m);
            nxt = m + logf(s) + emv;
        }
        __syncwarp();
        if (lane < NCL && mk) alphas[lane] = nxt;
        __syncwarp();
    }

    // logZ = lse(alpha + end_t)
    float v = (lane < NCL) ? alphas[lane] + end_t[lane] : -1e30f;
    float m = v;
#pragma unroll
    for (int off = 16; off > 0; off >>= 1) m = fmaxf(m, __shfl_xor_sync(0xFFFFFFFFu, m, off));
    float s = __expf(v - m);
#pragma unroll
    for (int off = 16; off > 0; off >>= 1) s += __shfl_xor_sync(0xFFFFFFFFu, s, off);
    if (lane == 0) {
        float logZ = m + logf(s);
        g_nll[b] = -(score - logZ);
    }
}

// ---------------- deterministic final sum ----------------
__global__ void sum_kernel(float* out) {
    float s = 0.0f;
    for (int b = 0; b < BB; b++) s += g_nll[b];
    out[0] = s;
}

// ---------------- launch ----------------
extern "C" void kernel_launch(void* const* d_in, const int* in_sizes, int n_in,
                              void* d_out, int out_size) {
    const float* word_table = (const float*)d_in[0];
    const float* char_table = (const float*)d_in[1];
    const float* conv_w     = (const float*)d_in[2];
    const float* conv_b     = (const float*)d_in[3];
    const float* w_ih_f     = (const float*)d_in[4];
    const float* w_hh_f     = (const float*)d_in[5];
    const float* b_f        = (const float*)d_in[6];
    const float* w_ih_r     = (const float*)d_in[7];
    const float* w_hh_r     = (const float*)d_in[8];
    const float* b_r        = (const float*)d_in[9];
    const float* lin_w      = (const float*)d_in[10];
    const float* lin_b      = (const float*)d_in[11];
    const float* start_t    = (const float*)d_in[12];
    const float* end_t      = (const float*)d_in[13];
    const float* trans      = (const float*)d_in[14];
    const int*   sent       = (const int*)d_in[15];
    const int*   word       = (const int*)d_in[16];
    const int*   tag        = (const int*)d_in[17];
    const unsigned* mask    = (const unsigned*)d_in[18];
    float* out = (float*)d_out;

    static int smem_set = 0;
    if (!smem_set) {
        cudaFuncSetAttribute(lstm_kernel, cudaFuncAttributeMaxDynamicSharedMemorySize, LSTM_SMEM);
        smem_set = 1;
    }

    init_kernel<<<1, 256>>>();
    mask_convert_kernel<<<32, 256>>>(mask);
    pad_w_kernel<<<(N2 * FP + 255) / 256, 256>>>(w_ih_f, w_ih_r);
    embed_conv_kernel<<<NROW, 128>>>(word_table, char_table, conv_w, conv_b, sent, word);
    gemm_gx_kernel<<<dim3(32, 128), 256>>>(b_f, b_r);
    lstm_kernel<<<128, 256, LSTM_SMEM>>>(w_hh_f, w_hh_r);
    emission_kernel<<<128, 256>>>(lin_w, lin_b);
    crf_kernel<<<64, 32>>>(tag, start_t, end_t, trans);
    sum_kernel<<<1, 1>>>(out);
}

// round 3
// speedup vs baseline: 1.1352x; 1.1352x over previous
#include <cuda_runtime.h>
#include <cuda_bf16.h>
#include <math.h>

// ---------------- problem constants ----------------
#define BB 64      // batch
#define SS 128     // seq len
#define LW 20      // chars per word
#define CE 30      // char emb
#define CC 30      // char conv channels
#define WE 300     // word emb
#define HH 256     // hidden
#define NCL 25     // num classes
#define FF 330     // feature = WE + CC
#define FP 336     // padded feature (multiple of 16)
#define NROW 8192  // S*B token rows
#define N2 2048    // 2 dirs * 4H

// ---------------- packed f32x2 helpers ----------------
#define FMA2(d, a, b) asm("fma.rn.f32x2 %0, %1, %2, %0;" : "+l"(d) : "l"(a), "l"(b))

__device__ __forceinline__ unsigned long long rep2(float x) {
    unsigned long long r;
    asm("mov.b64 %0, {%1, %1};" : "=l"(r) : "f"(x));
    return r;
}
__device__ __forceinline__ float2 unpk(unsigned long long v) {
    float2 f;
    asm("mov.b64 {%0, %1}, %2;" : "=f"(f.x), "=f"(f.y) : "l"(v));
    return f;
}

// ---------------- static device scratch ----------------
__device__ float g_feat[(size_t)NROW * FP];   // [s*64+b][FP]
__device__ float g_wpad[(size_t)N2 * FP];     // padded w_ih (fwd rows 0..1023, rev 1024..2047)
__device__ float g_gx[(size_t)NROW * N2];     // [(t*2048+col)*64 + b]
__device__ float g_hT[2 * 2 * BB * HH];       // [dir][parity][b][u] (b-major for vector staging)
__device__ float g_hseq[(size_t)NROW * 512];  // [(t*512+ug)*64 + b]
__device__ float g_em[(size_t)NROW * NCL];    // [(t*64+b)*25 + c]
__device__ int   g_mask[BB * SS];             // [b][t]
__device__ float g_nll[BB];
__device__ unsigned g_bar2[2];
__device__ volatile unsigned g_gen2[2];

__device__ __forceinline__ float sigf(float x) { return 1.0f / (1.0f + __expf(-x)); }

// ---------------- init ----------------
__global__ void init_kernel() {
    int tid = blockIdx.x * blockDim.x + threadIdx.x;
    if (tid == 0) { g_bar2[0] = 0u; g_bar2[1] = 0u; g_gen2[0] = 0u; g_gen2[1] = 0u; }
    for (int i = tid; i < 2 * 2 * BB * HH; i += blockDim.x * gridDim.x) g_hT[i] = 0.0f;
    if (tid < BB) g_nll[tid] = 0.0f;
}

// ---------------- mask dtype detect + convert ----------------
__global__ void mask_convert_kernel(const unsigned* __restrict__ m) {
    unsigned v0 = m[0];
    int mode;  // 0 = int32, 1 = bytes, 2 = float32
    if (v0 == 0x01010101u) mode = 1;
    else if (v0 == 0x3F800000u) mode = 2;
    else mode = 0;
    int tid = blockIdx.x * blockDim.x + threadIdx.x;
    if (tid >= BB * SS) return;
    int v;
    if (mode == 1) {
        const unsigned char* mb = (const unsigned char*)m;
        v = (mb[tid] != 0) ? 1 : 0;
    } else if (mode == 2) {
        const float* mf = (const float*)m;
        v = (mf[tid] != 0.0f) ? 1 : 0;
    } else {
        v = (m[tid] != 0u) ? 1 : 0;
    }
    g_mask[tid] = v;
}

// ---------------- pad w_ih into [2048][336] ----------------
__global__ void pad_w_kernel(const float* __restrict__ w_ih_f,
                             const float* __restrict__ w_ih_r) {
    int idx = blockIdx.x * blockDim.x + threadIdx.x;
    if (idx >= N2 * FP) return;
    int r = idx / FP, k = idx - r * FP;
    float v = 0.0f;
    if (k < FF) v = (r < 1024) ? w_ih_f[r * FF + k] : w_ih_r[(r - 1024) * FF + k];
    g_wpad[idx] = v;
}

// ---------------- char CNN + embedding concat -> feat ----------------
__global__ __launch_bounds__(128) void embed_conv_kernel(
    const float* __restrict__ word_table, const float* __restrict__ char_table,
    const float* __restrict__ conv_w, const float* __restrict__ conv_b,
    const int* __restrict__ sent, const int* __restrict__ word) {
    int tok = blockIdx.x;          // tok = b*128 + s
    int b = tok >> 7, s = tok & 127;
    int row = s * BB + b;          // seq-major row
    int tid = threadIdx.x;

    __shared__ float wsm[CC * CE * 3];    // 2700
    __shared__ float psm[(LW + 2) * CE];  // padded char emb [pos][ic]
    __shared__ float csm[CC * LW];        // conv outputs [oc][t]

    for (int i = tid; i < CC * CE * 3; i += 128) wsm[i] = conv_w[i];
    for (int i = tid; i < (LW + 2) * CE; i += 128) psm[i] = 0.0f;
    __syncthreads();
    for (int i = tid; i < LW * CE; i += 128) {
        int l = i / CE, e = i - l * CE;
        int c = word[tok * LW + l];
        psm[(l + 1) * CE + e] = (c == 0) ? 0.0f : char_table[c * CE + e];
    }
    __syncthreads();
    for (int idx = tid; idx < CC * LW; idx += 128) {
        int oc = idx / LW, t = idx - oc * LW;
        const float* wr = wsm + oc * (CE * 3);
        float sum = 0.0f;
#pragma unroll
        for (int k = 0; k < 3; k++) {
            const float* xr = psm + (t + k) * CE;
#pragma unroll
            for (int ic = 0; ic < CE; ic++) sum += xr[ic] * wr[ic * 3 + k];
        }
        csm[oc * LW + t] = sum;
    }
    // word embedding copy
    int widx = sent[tok];
    float* frow = g_feat + (size_t)row * FP;
    for (int i = tid; i < WE; i += 128) frow[i] = word_table[(size_t)widx * WE + i];
    __syncthreads();
    if (tid < CC) {
        float m = -1e30f;
#pragma unroll
        for (int t = 0; t < LW; t++) m = fmaxf(m, csm[tid * LW + t]);
        frow[WE + tid] = m + conv_b[tid];
    }
    if (tid >= CC && tid < CC + (FP - FF)) frow[WE + tid] = 0.0f;  // pad cols
}

// ---------------- gx GEMM: [8192 x 2048] = feat @ wpad^T, f32x2 packed ------
// 128x128 tiles, 8x8 microtile, KT=8. Grid (16, 64).
__global__ __launch_bounds__(256) void gemm_gx_kernel(const float* __restrict__ bf,
                                                      const float* __restrict__ br) {
    __shared__ float As[8][128];
    __shared__ float Bs[8][128];
    int bn = blockIdx.x * 128;
    int bm = blockIdx.y * 128;
    int tid = threadIdx.x;
    int tx = tid & 15, ty = tid >> 4;

    int lr = tid >> 1;          // 0..127
    int lc = (tid & 1) * 4;     // 0 or 4

    unsigned long long acc[8][4];
#pragma unroll
    for (int i = 0; i < 8; i++)
#pragma unroll
        for (int j = 0; j < 4; j++) acc[i][j] = 0ull;

    const float* Aptr = g_feat + (size_t)(bm + lr) * FP + lc;
    const float* Bptr = g_wpad + (size_t)(bn + lr) * FP + lc;

    for (int k0 = 0; k0 < FP; k0 += 8) {
        float4 av = *(const float4*)(Aptr + k0);
        float4 bv = *(const float4*)(Bptr + k0);
        __syncthreads();
        As[lc + 0][lr] = av.x; As[lc + 1][lr] = av.y; As[lc + 2][lr] = av.z; As[lc + 3][lr] = av.w;
        Bs[lc + 0][lr] = bv.x; Bs[lc + 1][lr] = bv.y; Bs[lc + 2][lr] = bv.z; Bs[lc + 3][lr] = bv.w;
        __syncthreads();
#pragma unroll
        for (int kk = 0; kk < 8; kk++) {
            float4 a0 = *(const float4*)&As[kk][ty * 8];
            float4 a1 = *(const float4*)&As[kk][ty * 8 + 4];
            ulonglong2 bq0 = *(const ulonglong2*)&Bs[kk][tx * 8];
            ulonglong2 bq1 = *(const ulonglong2*)&Bs[kk][tx * 8 + 4];
            float ar[8] = {a0.x, a0.y, a0.z, a0.w, a1.x, a1.y, a1.z, a1.w};
#pragma unroll
            for (int i = 0; i < 8; i++) {
                unsigned long long rp = rep2(ar[i]);
                FMA2(acc[i][0], rp, bq0.x);
                FMA2(acc[i][1], rp, bq0.y);
                FMA2(acc[i][2], rp, bq1.x);
                FMA2(acc[i][3], rp, bq1.y);
            }
        }
    }

    // epilogue: thread covers rows bm+ty*8 .. +7 (same t), cols bn+tx*8 .. +7
    int m0 = bm + ty * 8;
    int t = m0 >> 6;
    int b0 = m0 & 63;
    float2 u[8][4];
#pragma unroll
    for (int i = 0; i < 8; i++)
#pragma unroll
        for (int j = 0; j < 4; j++) u[i][j] = unpk(acc[i][j]);
#pragma unroll
    for (int j = 0; j < 8; j++) {
        int n = bn + tx * 8 + j;
        float bias = (n < 1024) ? bf[n] : br[n - 1024];
        int jp = j >> 1, jh = j & 1;
        float v[8];
#pragma unroll
        for (int i = 0; i < 8; i++) v[i] = (jh ? u[i][jp].y : u[i][jp].x) + bias;
        float* dst = &g_gx[((size_t)t * N2 + n) * 64 + b0];
        *(float4*)dst = make_float4(v[0], v[1], v[2], v[3]);
        *(float4*)(dst + 4) = make_float4(v[4], v[5], v[6], v[7]);
    }
}

// ---------------- per-direction grid barrier (64 blocks each) ----------------
__device__ __forceinline__ void grid_barrier(int dir) {
    __syncthreads();
    if (threadIdx.x == 0) {
        __threadfence();
        unsigned gen = g_gen2[dir];
        if (atomicAdd(&g_bar2[dir], 1u) == 63u) {
            g_bar2[dir] = 0u;
            __threadfence();
            g_gen2[dir] = gen + 1u;
        } else {
            while (g_gen2[dir] == gen) { __nanosleep(32); }
        }
    }
    __syncthreads();
}

// ---------------- persistent bidirectional LSTM ----------------
// 128 blocks: 0..63 fwd, 64..127 rev. Block owns 4 hidden units (16 gate rows)
// x 64 batch. GEMV lanes: 16 rows x 2; warp w covers batches w*8..w*8+7.
// h staged in smem [b][260] (vector LDS.128, conflict-free), W broadcast.
#define LSTM_SMEM ((16 * 260 + 64 * 260 + 16 * 68) * 4)
__global__ __launch_bounds__(256, 1) void lstm_kernel(const float* __restrict__ whh_f,
                                                      const float* __restrict__ whh_r) {
    extern __shared__ float sm[];
    float* Ws = sm;                          // [16][260] gate rows (r = g*4 + jj)
    float* Hs = sm + 16 * 260;               // [64][260]
    float* Pre = sm + 16 * 260 + 64 * 260;   // [16][68]

    int dir = blockIdx.x >> 6;
    int u0 = (blockIdx.x & 63) * 4;
    const float* whh = dir ? whh_r : whh_f;
    int tid = threadIdx.x;

    // gemv roles
    int lane = tid & 31, w = tid >> 5;
    int r = lane & 15;     // gate row 0..15
    int bh = lane >> 4;    // 0/1
    int bbase = w * 8 + bh * 4;
    // activation roles
    int ab = tid & 63, au = tid >> 6;  // batch, unit 0..3

    // load W_hh slice: Ws[r = g*4+jj][k] = whh[g*256 + u0 + jj][k]
    for (int i = tid; i < 16 * 256; i += 256) {
        int rr = i >> 8, k = i & 255;
        int g = rr >> 2, jj = rr & 3;
        Ws[rr * 260 + k] = whh[(size_t)(g * 256 + u0 + jj) * 256 + k];
    }

    float c = 0.0f;
    int p = 0;

    for (int step = 0; step < 128; step++) {
        int t = dir ? (127 - step) : step;
        if (step) grid_barrier(dir);
        else __syncthreads();  // Ws visible

        // stage prev h: g_hT[dir][p][b][256] -> Hs[b][260] (L2 reads, bypass L1)
        const float4* src = (const float4*)(g_hT + (size_t)(dir * 2 + p) * (BB * HH));
        for (int i = tid; i < 4096; i += 256) {
            float4 v = __ldcg(src + i);
            int e = i << 2;
            *(float4*)&Hs[(e >> 8) * 260 + (e & 255)] = v;
        }
        __syncthreads();

        // GEMV: Pre[r][b] = sum_k Ws[r][k] * Hs[b][k], 4 batches/thread, f32x2
        {
            unsigned long long A0 = 0ull, A1 = 0ull, A2 = 0ull, A3 = 0ull;
            const float* wrow = Ws + r * 260;
            const float* h0 = Hs + (bbase + 0) * 260;
            const float* h1 = Hs + (bbase + 1) * 260;
            const float* h2 = Hs + (bbase + 2) * 260;
            const float* h3 = Hs + (bbase + 3) * 260;
#pragma unroll 8
            for (int k = 0; k < 256; k += 4) {
                ulonglong2 wv = *(const ulonglong2*)(wrow + k);
                ulonglong2 x0 = *(const ulonglong2*)(h0 + k);
                ulonglong2 x1 = *(const ulonglong2*)(h1 + k);
                ulonglong2 x2 = *(const ulonglong2*)(h2 + k);
                ulonglong2 x3 = *(const ulonglong2*)(h3 + k);
                FMA2(A0, wv.x, x0.x); FMA2(A0, wv.y, x0.y);
                FMA2(A1, wv.x, x1.x); FMA2(A1, wv.y, x1.y);
                FMA2(A2, wv.x, x2.x); FMA2(A2, wv.y, x2.y);
                FMA2(A3, wv.x, x3.x); FMA2(A3, wv.y, x3.y);
            }
            float2 f0 = unpk(A0), f1 = unpk(A1), f2 = unpk(A2), f3 = unpk(A3);
            Pre[r * 68 + bbase + 0] = f0.x + f0.y;
            Pre[r * 68 + bbase + 1] = f1.x + f1.y;
            Pre[r * 68 + bbase + 2] = f2.x + f2.y;
            Pre[r * 68 + bbase + 3] = f3.x + f3.y;
        }
        __syncthreads();

        // activation: thread (au, ab)
        size_t gxb = ((size_t)t * N2 + dir * 1024 + u0 + au) * 64 + ab;
        float a0 = g_gx[gxb + 0 * 256 * 64] + Pre[(0 * 4 + au) * 68 + ab];
        float a1 = g_gx[gxb + 1 * 256 * 64] + Pre[(1 * 4 + au) * 68 + ab];
        float a2 = g_gx[gxb + 2 * 256 * 64] + Pre[(2 * 4 + au) * 68 + ab];
        float a3 = g_gx[gxb + 3 * 256 * 64] + Pre[(3 * 4 + au) * 68 + ab];

        float ig = sigf(a0), fg = sigf(a1), gg = tanhf(a2), og = sigf(a3);
        c = fg * c + ig * gg;
        float h = og * tanhf(c);

        int pn = p ^ 1;
        g_hT[(size_t)(dir * 2 + pn) * (BB * HH) + ab * 256 + (u0 + au)] = h;
        g_hseq[((size_t)t * 512 + dir * 256 + u0 + au) * 64 + ab] = h;
        p = pn;
    }
}

// ---------------- emission: em = h @ lin_w^T + lin_b ----------------
// lin_w staged in dynamic smem; static-unrolled class loop (no local-mem spill)
#define EM_SMEM (NCL * 512 * 4)
__global__ __launch_bounds__(256) void emission_kernel(const float* __restrict__ lin_w,
                                                       const float* __restrict__ lin_b) {
    extern __shared__ float EWs[];
    int t = blockIdx.x;
    int tid = threadIdx.x;
    for (int i = tid; i < NCL * 512; i += 256) EWs[i] = lin_w[i];
    __syncthreads();

    int b = tid & 63, cg = tid >> 6;  // cg 0..3, classes cg*7+ci
    float acc[7];
#pragma unroll
    for (int ci = 0; ci < 7; ci++) {
        int c0 = cg * 7 + ci;
        acc[ci] = (c0 < NCL) ? lin_b[c0] : 0.0f;
    }
    const float* hp = g_hseq + (size_t)t * 512 * 64 + b;
#pragma unroll 4
    for (int u = 0; u < 512; u++) {
        float hv = hp[(size_t)u * 64];
#pragma unroll
        for (int ci = 0; ci < 7; ci++) {
            int c0 = cg * 7 + ci;
            if (c0 < NCL) acc[ci] += hv * EWs[c0 * 512 + u];
        }
    }
#pragma unroll
    for (int ci = 0; ci < 7; ci++) {
        int c0 = cg * 7 + ci;
        if (c0 < NCL) g_em[((size_t)t * 64 + b) * NCL + c0] = acc[ci];
    }
}

// ---------------- CRF NLL (one block per batch, 1 warp) ----------------
__global__ __launch_bounds__(32) void crf_kernel(const int* __restrict__ tag,
                                                 const float* __restrict__ start_t,
                                                 const float* __restrict__ end_t,
                                                 const float* __restrict__ trans) {
    int b = blockIdx.x;
    int lane = threadIdx.x;

    __shared__ float tr[NCL * NCL];
    __shared__ float alphas[32];

    for (int i = lane; i < NCL * NCL; i += 32) tr[i] = trans[i];
    __syncwarp();

    // gold-path score + length
    float myscore = 0.0f;
    int mylen = 0;
    for (int t = lane; t < SS; t += 32) {
        int mk = g_mask[b * SS + t];
        mylen += mk;
        int tgt = tag[b * SS + t];
        if (t == 0) {
            myscore += start_t[tgt] + g_em[(size_t)b * NCL + tgt];
        } else if (mk) {
            int tgp = tag[b * SS + t - 1];
            myscore += tr[tgp * NCL + tgt] + g_em[((size_t)t * 64 + b) * NCL + tgt];
        }
    }
#pragma unroll
    for (int off = 16; off > 0; off >>= 1) {
        myscore += __shfl_xor_sync(0xFFFFFFFFu, myscore, off);
        mylen += __shfl_xor_sync(0xFFFFFFFFu, mylen, off);
    }
    float score = 0.0f;
    if (lane == 0) {
        int last = mylen - 1;
        score = myscore + end_t[tag[b * SS + last]];
    }

    // forward algorithm
    if (lane < NCL) alphas[lane] = start_t[lane] + g_em[(size_t)b * NCL + lane];
    __syncwarp();

    for (int t = 1; t < SS; t++) {
        int mk = g_mask[b * SS + t];
        float nxt = 0.0f;
        if (lane < NCL) {
            float emv = g_em[((size_t)t * 64 + b) * NCL + lane];
            float m = -1e30f;
#pragma unroll
            for (int i = 0; i < NCL; i++) m = fmaxf(m, alphas[i] + tr[i * NCL + lane]);
            float s = 0.0f;
#pragma unroll
            for (int i = 0; i < NCL; i++) s += __expf(alphas[i] + tr[i * NCL + lane] - m);
            nxt = m + logf(s) + emv;
        }
        __syncwarp();
        if (lane < NCL && mk) alphas[lane] = nxt;
        __syncwarp();
    }

    float v = (lane < NCL) ? alphas[lane] + end_t[lane] : -1e30f;
    float m = v;
#pragma unroll
    for (int off = 16; off > 0; off >>= 1) m = fmaxf(m, __shfl_xor_sync(0xFFFFFFFFu, m, off));
    float s = __expf(v - m);
#pragma unroll
    for (int off = 16; off > 0; off >>= 1) s += __shfl_xor_sync(0xFFFFFFFFu, s, off);
    if (lane == 0) {
        float logZ = m + logf(s);
        g_nll[b] = -(score - logZ);
    }
}

// ---------------- deterministic final sum ----------------
__global__ void sum_kernel(float* out) {
    float s = 0.0f;
    for (int b = 0; b < BB; b++) s += g_nll[b];
    out[0] = s;
}

// ---------------- launch ----------------
extern "C" void kernel_launch(void* const* d_in, const int* in_sizes, int n_in,
                              void* d_out, int out_size) {
    const float* word_table = (const float*)d_in[0];
    const float* char_table = (const float*)d_in[1];
    const float* conv_w     = (const float*)d_in[2];
    const float* conv_b     = (const float*)d_in[3];
    const float* w_ih_f     = (const float*)d_in[4];
    const float* w_hh_f     = (const float*)d_in[5];
    const float* b_f        = (const float*)d_in[6];
    const float* w_ih_r     = (const float*)d_in[7];
    const float* w_hh_r     = (const float*)d_in[8];
    const float* b_r        = (const float*)d_in[9];
    const float* lin_w      = (const float*)d_in[10];
    const float* lin_b      = (const float*)d_in[11];
    const float* start_t    = (const float*)d_in[12];
    const float* end_t      = (const float*)d_in[13];
    const float* trans      = (const float*)d_in[14];
    const int*   sent       = (const int*)d_in[15];
    const int*   word       = (const int*)d_in[16];
    const int*   tag        = (const int*)d_in[17];
    const unsigned* mask    = (const unsigned*)d_in[18];
    float* out = (float*)d_out;

    static int smem_set = 0;
    if (!smem_set) {
        cudaFuncSetAttribute(lstm_kernel, cudaFuncAttributeMaxDynamicSharedMemorySize, LSTM_SMEM);
        cudaFuncSetAttribute(emission_kernel, cudaFuncAttributeMaxDynamicSharedMemorySize, EM_SMEM);
        smem_set = 1;
    }

    init_kernel<<<1, 256>>>();
    mask_convert_kernel<<<32, 256>>>(mask);
    pad_w_kernel<<<(N2 * FP + 255) / 256, 256>>>(w_ih_f, w_ih_r);
    embed_conv_kernel<<<NROW, 128>>>(word_table, char_table, conv_w, conv_b, sent, word);
    gemm_gx_kernel<<<dim3(16, 64), 256>>>(b_f, b_r);
    lstm_kernel<<<128, 256, LSTM_SMEM>>>(w_hh_f, w_hh_r);
    emission_kernel<<<128, 256, EM_SMEM>>>(lin_w, lin_b);
    crf_kernel<<<64, 32>>>(tag, start_t, end_t, trans);
    sum_kernel<<<1, 1>>>(out);
}

// round 4
// speedup vs baseline: 1.2822x; 1.1295x over previous
#include <cuda_runtime.h>
#include <cuda_bf16.h>
#include <math.h>

// ---------------- problem constants ----------------
#define BB 64      // batch
#define SS 128     // seq len
#define LW 20      // chars per word
#define CE 30      // char emb
#define CC 30      // char conv channels
#define WE 300     // word emb
#define HH 256     // hidden
#define NCL 25     // num classes
#define FF 330     // feature = WE + CC
#define FP 336     // padded feature (multiple of 16)
#define NROW 8192  // S*B token rows
#define N2 2048    // 2 dirs * 4H

// ---------------- packed f32x2 helpers ----------------
#define FMA2(d, a, b) asm("fma.rn.f32x2 %0, %1, %2, %0;" : "+l"(d) : "l"(a), "l"(b))

__device__ __forceinline__ unsigned long long rep2(float x) {
    unsigned long long r;
    asm("mov.b64 %0, {%1, %1};" : "=l"(r) : "f"(x));
    return r;
}
__device__ __forceinline__ float2 unpk(unsigned long long v) {
    float2 f;
    asm("mov.b64 {%0, %1}, %2;" : "=f"(f.x), "=f"(f.y) : "l"(v));
    return f;
}

// ---------------- static device scratch ----------------
__device__ float g_feat[(size_t)NROW * FP];   // [s*64+b][FP]
__device__ float g_wpad[(size_t)N2 * FP];     // padded w_ih
__device__ float g_gx[(size_t)NROW * N2];     // [(t*2048+col)*64 + b]
__device__ float g_hT[2 * 2 * BB * HH];       // [dir][parity][b][u]
__device__ float g_hseq[(size_t)NROW * 512];  // [(t*512+ug)*64 + b]
__device__ float g_em[(size_t)NROW * NCL];    // [(t*64+b)*25 + c]
__device__ int   g_mask[BB * SS];             // [b][t]
__device__ float g_nll[BB];
__device__ unsigned g_cnt[2][SS];             // per-step arrival counters

__device__ __forceinline__ float sigf(float x) { return 1.0f / (1.0f + __expf(-x)); }

// ---------------- init ----------------
__global__ void init_kernel() {
    int tid = blockIdx.x * blockDim.x + threadIdx.x;
    for (int i = tid; i < 2 * SS; i += blockDim.x * gridDim.x) ((unsigned*)g_cnt)[i] = 0u;
    for (int i = tid; i < 2 * 2 * BB * HH; i += blockDim.x * gridDim.x) g_hT[i] = 0.0f;
    if (tid < BB) g_nll[tid] = 0.0f;
}

// ---------------- mask dtype detect + convert ----------------
__global__ void mask_convert_kernel(const unsigned* __restrict__ m) {
    unsigned v0 = m[0];
    int mode;  // 0 = int32, 1 = bytes, 2 = float32
    if (v0 == 0x01010101u) mode = 1;
    else if (v0 == 0x3F800000u) mode = 2;
    else mode = 0;
    int tid = blockIdx.x * blockDim.x + threadIdx.x;
    if (tid >= BB * SS) return;
    int v;
    if (mode == 1) {
        const unsigned char* mb = (const unsigned char*)m;
        v = (mb[tid] != 0) ? 1 : 0;
    } else if (mode == 2) {
        const float* mf = (const float*)m;
        v = (mf[tid] != 0.0f) ? 1 : 0;
    } else {
        v = (m[tid] != 0u) ? 1 : 0;
    }
    g_mask[tid] = v;
}

// ---------------- pad w_ih into [2048][336] ----------------
__global__ void pad_w_kernel(const float* __restrict__ w_ih_f,
                             const float* __restrict__ w_ih_r) {
    int idx = blockIdx.x * blockDim.x + threadIdx.x;
    if (idx >= N2 * FP) return;
    int r = idx / FP, k = idx - r * FP;
    float v = 0.0f;
    if (k < FF) v = (r < 1024) ? w_ih_f[r * FF + k] : w_ih_r[(r - 1024) * FF + k];
    g_wpad[idx] = v;
}

// ---------------- char CNN + embedding concat -> feat (v2) ----------------
// 128 threads = 4 warps, 1 token/warp. Lane = out-channel, conv weights in
// registers, x read as broadcast float4 from 32-padded psm rows.
__global__ __launch_bounds__(128) void embed_conv_kernel(
    const float* __restrict__ word_table, const float* __restrict__ char_table,
    const float* __restrict__ conv_w, const float* __restrict__ conv_b,
    const int* __restrict__ sent, const int* __restrict__ word) {
    __shared__ float wsm[CC * CE * 3];   // 2700
    __shared__ float psm[4][22 * 32];    // per-warp padded char emb [pos][ic(32)]
    __shared__ int   cids[4][LW];

    int tid = threadIdx.x, w = tid >> 5, lane = tid & 31;
    int tok = blockIdx.x * 4 + w;        // tok = b*128 + s
    int b = tok >> 7, s = tok & 127;
    int row = s * BB + b;

    for (int i = tid; i < CC * CE * 3; i += 128) wsm[i] = conv_w[i];
    float* pw = psm[w];
    for (int i = lane; i < 22 * 32; i += 32) pw[i] = 0.0f;
    if (lane < LW) cids[w][lane] = word[tok * LW + lane];
    __syncthreads();

    // fill psm rows 1..20 (row 0 and 21 stay zero; cols 30,31 stay zero)
    for (int pos = 0; pos < LW; pos++) {
        if (lane < CE) {
            int c = cids[w][pos];
            pw[(pos + 1) * 32 + lane] = (c == 0) ? 0.0f : char_table[c * CE + lane];
        }
    }

    // word embedding copy (300 floats = 75 float4, both 16B aligned)
    int widx = sent[tok];
    float* frow = g_feat + (size_t)row * FP;
    {
        const float4* wt = (const float4*)(word_table + (size_t)widx * WE);
        float4* fr4 = (float4*)frow;
        for (int j = lane; j < 75; j += 32) fr4[j] = wt[j];
    }
    __syncwarp();

    // conv: lane oc, weights in regs, x broadcast
    int oc = (lane < CC) ? lane : 0;
    float wreg[3][32];
#pragma unroll
    for (int k = 0; k < 3; k++)
#pragma unroll
        for (int ic = 0; ic < 32; ic++)
            wreg[k][ic] = (ic < CC) ? wsm[oc * 90 + ic * 3 + k] : 0.0f;

    float m = -1e30f;
    for (int t = 0; t < LW; t++) {
        float asum = 0.0f;
#pragma unroll
        for (int k = 0; k < 3; k++) {
            const float4* xr = (const float4*)(pw + (t + k) * 32);
            float acc = 0.0f;
#pragma unroll
            for (int j = 0; j < 8; j++) {
                float4 x = xr[j];
                acc += x.x * wreg[k][j * 4 + 0] + x.y * wreg[k][j * 4 + 1]
                     + x.z * wreg[k][j * 4 + 2] + x.w * wreg[k][j * 4 + 3];
            }
            asum += acc;
        }
        m = fmaxf(m, asum);
    }
    if (lane < CC) frow[WE + lane] = m + conv_b[lane];
    if (lane < (FP - FF)) frow[FF + lane] = 0.0f;
}

// ---------------- gx GEMM: double-buffered, f32x2 packed ----------------
// 128x128 tiles, 8x8 microtile, KT=8, 42 k-tiles, 1 sync/iter.
__global__ __launch_bounds__(256) void gemm_gx_kernel(const float* __restrict__ bf,
                                                      const float* __restrict__ br) {
    __shared__ float As[2][8][128];
    __shared__ float Bs[2][8][128];
    int bn = blockIdx.x * 128;
    int bm = blockIdx.y * 128;
    int tid = threadIdx.x;
    int tx = tid & 15, ty = tid >> 4;
    int lr = tid >> 1, lc = (tid & 1) * 4;

    unsigned long long acc[8][4];
#pragma unroll
    for (int i = 0; i < 8; i++)
#pragma unroll
        for (int j = 0; j < 4; j++) acc[i][j] = 0ull;

    const float* Aptr = g_feat + (size_t)(bm + lr) * FP + lc;
    const float* Bptr = g_wpad + (size_t)(bn + lr) * FP + lc;

    float4 av = *(const float4*)Aptr;
    float4 bv = *(const float4*)Bptr;

#pragma unroll 1
    for (int kt = 0; kt < 42; kt++) {
        int buf = kt & 1;
        As[buf][lc + 0][lr] = av.x; As[buf][lc + 1][lr] = av.y;
        As[buf][lc + 2][lr] = av.z; As[buf][lc + 3][lr] = av.w;
        Bs[buf][lc + 0][lr] = bv.x; Bs[buf][lc + 1][lr] = bv.y;
        Bs[buf][lc + 2][lr] = bv.z; Bs[buf][lc + 3][lr] = bv.w;
        __syncthreads();
        if (kt < 41) {
            av = *(const float4*)(Aptr + (kt + 1) * 8);
            bv = *(const float4*)(Bptr + (kt + 1) * 8);
        }
#pragma unroll
        for (int kk = 0; kk < 8; kk++) {
            float4 a0 = *(const float4*)&As[buf][kk][ty * 8];
            float4 a1 = *(const float4*)&As[buf][kk][ty * 8 + 4];
            ulonglong2 bq0 = *(const ulonglong2*)&Bs[buf][kk][tx * 8];
            ulonglong2 bq1 = *(const ulonglong2*)&Bs[buf][kk][tx * 8 + 4];
            float ar[8] = {a0.x, a0.y, a0.z, a0.w, a1.x, a1.y, a1.z, a1.w};
#pragma unroll
            for (int i = 0; i < 8; i++) {
                unsigned long long rp = rep2(ar[i]);
                FMA2(acc[i][0], rp, bq0.x);
                FMA2(acc[i][1], rp, bq0.y);
                FMA2(acc[i][2], rp, bq1.x);
                FMA2(acc[i][3], rp, bq1.y);
            }
        }
    }

    int m0 = bm + ty * 8;
    int t = m0 >> 6;
    int b0 = m0 & 63;
    float2 u[8][4];
#pragma unroll
    for (int i = 0; i < 8; i++)
#pragma unroll
        for (int j = 0; j < 4; j++) u[i][j] = unpk(acc[i][j]);
#pragma unroll
    for (int j = 0; j < 8; j++) {
        int n = bn + tx * 8 + j;
        float bias = (n < 1024) ? bf[n] : br[n - 1024];
        int jp = j >> 1, jh = j & 1;
        float v[8];
#pragma unroll
        for (int i = 0; i < 8; i++) v[i] = (jh ? u[i][jp].y : u[i][jp].x) + bias;
        float* dst = &g_gx[((size_t)t * N2 + n) * 64 + b0];
        *(float4*)dst = make_float4(v[0], v[1], v[2], v[3]);
        *(float4*)(dst + 4) = make_float4(v[4], v[5], v[6], v[7]);
    }
}

// ---------------- per-direction, per-step arrival barrier ----------------
__device__ __forceinline__ void grid_barrier(int dir, int step) {
    __syncthreads();
    if (threadIdx.x == 0) {
        __threadfence();
        atomicAdd(&g_cnt[dir][step], 1u);
        volatile unsigned* c = &g_cnt[dir][step];
        while (*c < 64u) {}
    }
    __syncthreads();
}

// ---------------- persistent bidirectional LSTM ----------------
#define LSTM_SMEM ((16 * 260 + 64 * 260 + 16 * 68) * 4)
__global__ __launch_bounds__(256, 1) void lstm_kernel(const float* __restrict__ whh_f,
                                                      const float* __restrict__ whh_r) {
    extern __shared__ float sm[];
    float* Ws = sm;                          // [16][260] gate rows (r = g*4 + jj)
    float* Hs = sm + 16 * 260;               // [64][260]
    float* Pre = sm + 16 * 260 + 64 * 260;   // [16][68]

    int dir = blockIdx.x >> 6;
    int u0 = (blockIdx.x & 63) * 4;
    const float* whh = dir ? whh_r : whh_f;
    int tid = threadIdx.x;

    int lane = tid & 31, w = tid >> 5;
    int r = lane & 15;
    int bh = lane >> 4;
    int bbase = w * 8 + bh * 4;
    int ab = tid & 63, au = tid >> 6;

    for (int i = tid; i < 16 * 256; i += 256) {
        int rr = i >> 8, k = i & 255;
        int g = rr >> 2, jj = rr & 3;
        Ws[rr * 260 + k] = whh[(size_t)(g * 256 + u0 + jj) * 256 + k];
    }

    float c = 0.0f;
    int p = 0;

    for (int step = 0; step < 128; step++) {
        int t = dir ? (127 - step) : step;

        // prefetch gx for this step (independent of the barrier)
        size_t gxb = ((size_t)t * N2 + dir * 1024 + u0 + au) * 64 + ab;
        float ga0 = g_gx[gxb + 0 * 256 * 64];
        float ga1 = g_gx[gxb + 1 * 256 * 64];
        float ga2 = g_gx[gxb + 2 * 256 * 64];
        float ga3 = g_gx[gxb + 3 * 256 * 64];

        if (step) grid_barrier(dir, step);
        else __syncthreads();

        // stage prev h: g_hT[dir][p][b][256] -> Hs[b][260]
        const float4* src = (const float4*)(g_hT + (size_t)(dir * 2 + p) * (BB * HH));
        for (int i = tid; i < 4096; i += 256) {
            float4 v = __ldcg(src + i);
            int e = i << 2;
            *(float4*)&Hs[(e >> 8) * 260 + (e & 255)] = v;
        }
        __syncthreads();

        // GEMV: Pre[r][b] = sum_k Ws[r][k] * Hs[b][k]
        {
            unsigned long long A0 = 0ull, A1 = 0ull, A2 = 0ull, A3 = 0ull;
            const float* wrow = Ws + r * 260;
            const float* h0 = Hs + (bbase + 0) * 260;
            const float* h1 = Hs + (bbase + 1) * 260;
            const float* h2 = Hs + (bbase + 2) * 260;
            const float* h3 = Hs + (bbase + 3) * 260;
#pragma unroll 8
            for (int k = 0; k < 256; k += 4) {
                ulonglong2 wv = *(const ulonglong2*)(wrow + k);
                ulonglong2 x0 = *(const ulonglong2*)(h0 + k);
                ulonglong2 x1 = *(const ulonglong2*)(h1 + k);
                ulonglong2 x2 = *(const ulonglong2*)(h2 + k);
                ulonglong2 x3 = *(const ulonglong2*)(h3 + k);
                FMA2(A0, wv.x, x0.x); FMA2(A0, wv.y, x0.y);
                FMA2(A1, wv.x, x1.x); FMA2(A1, wv.y, x1.y);
                FMA2(A2, wv.x, x2.x); FMA2(A2, wv.y, x2.y);
                FMA2(A3, wv.x, x3.x); FMA2(A3, wv.y, x3.y);
            }
            float2 f0 = unpk(A0), f1 = unpk(A1), f2 = unpk(A2), f3 = unpk(A3);
            Pre[r * 68 + bbase + 0] = f0.x + f0.y;
            Pre[r * 68 + bbase + 1] = f1.x + f1.y;
            Pre[r * 68 + bbase + 2] = f2.x + f2.y;
            Pre[r * 68 + bbase + 3] = f3.x + f3.y;
        }
        __syncthreads();

        float a0 = ga0 + Pre[(0 * 4 + au) * 68 + ab];
        float a1 = ga1 + Pre[(1 * 4 + au) * 68 + ab];
        float a2 = ga2 + Pre[(2 * 4 + au) * 68 + ab];
        float a3 = ga3 + Pre[(3 * 4 + au) * 68 + ab];

        float ig = sigf(a0), fg = sigf(a1), gg = tanhf(a2), og = sigf(a3);
        c = fg * c + ig * gg;
        float h = og * tanhf(c);

        int pn = p ^ 1;
        g_hT[(size_t)(dir * 2 + pn) * (BB * HH) + ab * 256 + (u0 + au)] = h;
        g_hseq[((size_t)t * 512 + dir * 256 + u0 + au) * 64 + ab] = h;
        p = pn;
    }
}

// ---------------- emission: em = h @ lin_w^T + lin_b ----------------
#define EM_SMEM (NCL * 512 * 4)
__global__ __launch_bounds__(256) void emission_kernel(const float* __restrict__ lin_w,
                                                       const float* __restrict__ lin_b) {
    extern __shared__ float EWs[];
    int t = blockIdx.x;
    int tid = threadIdx.x;
    for (int i = tid; i < NCL * 512; i += 256) EWs[i] = lin_w[i];
    __syncthreads();

    int b = tid & 63, cg = tid >> 6;
    float acc[7];
#pragma unroll
    for (int ci = 0; ci < 7; ci++) {
        int c0 = cg * 7 + ci;
        acc[ci] = (c0 < NCL) ? lin_b[c0] : 0.0f;
    }
    const float* hp = g_hseq + (size_t)t * 512 * 64 + b;
#pragma unroll 4
    for (int u = 0; u < 512; u++) {
        float hv = hp[(size_t)u * 64];
#pragma unroll
        for (int ci = 0; ci < 7; ci++) {
            int c0 = cg * 7 + ci;
            if (c0 < NCL) acc[ci] += hv * EWs[c0 * 512 + u];
        }
    }
#pragma unroll
    for (int ci = 0; ci < 7; ci++) {
        int c0 = cg * 7 + ci;
        if (c0 < NCL) g_em[((size_t)t * 64 + b) * NCL + c0] = acc[ci];
    }
}

// ---------------- CRF NLL (one block per batch, 1 warp) ----------------
__global__ __launch_bounds__(32) void crf_kernel(const int* __restrict__ tag,
                                                 const float* __restrict__ start_t,
                                                 const float* __restrict__ end_t,
                                                 const float* __restrict__ trans) {
    int b = blockIdx.x;
    int lane = threadIdx.x;

    __shared__ float tr[NCL * NCL];
    __shared__ float alphas[32];

    for (int i = lane; i < NCL * NCL; i += 32) tr[i] = trans[i];
    __syncwarp();

    float myscore = 0.0f;
    int mylen = 0;
    for (int t = lane; t < SS; t += 32) {
        int mk = g_mask[b * SS + t];
        mylen += mk;
        int tgt = tag[b * SS + t];
        if (t == 0) {
            myscore += start_t[tgt] + g_em[(size_t)b * NCL + tgt];
        } else if (mk) {
            int tgp = tag[b * SS + t - 1];
            myscore += tr[tgp * NCL + tgt] + g_em[((size_t)t * 64 + b) * NCL + tgt];
        }
    }
#pragma unroll
    for (int off = 16; off > 0; off >>= 1) {
        myscore += __shfl_xor_sync(0xFFFFFFFFu, myscore, off);
        mylen += __shfl_xor_sync(0xFFFFFFFFu, mylen, off);
    }
    float score = 0.0f;
    if (lane == 0) {
        int last = mylen - 1;
        score = myscore + end_t[tag[b * SS + last]];
    }

    if (lane < NCL) alphas[lane] = start_t[lane] + g_em[(size_t)b * NCL + lane];
    __syncwarp();

    for (int t = 1; t < SS; t++) {
        int mk = g_mask[b * SS + t];
        float nxt = 0.0f;
        if (lane < NCL) {
            float emv = g_em[((size_t)t * 64 + b) * NCL + lane];
            float m = -1e30f;
#pragma unroll
            for (int i = 0; i < NCL; i++) m = fmaxf(m, alphas[i] + tr[i * NCL + lane]);
            float s = 0.0f;
#pragma unroll
            for (int i = 0; i < NCL; i++) s += __expf(alphas[i] + tr[i * NCL + lane] - m);
            nxt = m + logf(s) + emv;
        }
        __syncwarp();
        if (lane < NCL && mk) alphas[lane] = nxt;
        __syncwarp();
    }

    float v = (lane < NCL) ? alphas[lane] + end_t[lane] : -1e30f;
    float m = v;
#pragma unroll
    for (int off = 16; off > 0; off >>= 1) m = fmaxf(m, __shfl_xor_sync(0xFFFFFFFFu, m, off));
    float s = __expf(v - m);
#pragma unroll
    for (int off = 16; off > 0; off >>= 1) s += __shfl_xor_sync(0xFFFFFFFFu, s, off);
    if (lane == 0) {
        float logZ = m + logf(s);
        g_nll[b] = -(score - logZ);
    }
}

// ---------------- deterministic final sum ----------------
__global__ void sum_kernel(float* out) {
    int lane = threadIdx.x;
    float s = g_nll[lane] + g_nll[lane + 32];
#pragma unroll
    for (int off = 16; off > 0; off >>= 1) s += __shfl_xor_sync(0xFFFFFFFFu, s, off);
    if (lane == 0) out[0] = s;
}

// ---------------- launch ----------------
extern "C" void kernel_launch(void* const* d_in, const int* in_sizes, int n_in,
                              void* d_out, int out_size) {
    const float* word_table = (const float*)d_in[0];
    const float* char_table = (const float*)d_in[1];
    const float* conv_w     = (const float*)d_in[2];
    const float* conv_b     = (const float*)d_in[3];
    const float* w_ih_f     = (const float*)d_in[4];
    const float* w_hh_f     = (const float*)d_in[5];
    const float* b_f        = (const float*)d_in[6];
    const float* w_ih_r     = (const float*)d_in[7];
    const float* w_hh_r     = (const float*)d_in[8];
    const float* b_r        = (const float*)d_in[9];
    const float* lin_w      = (const float*)d_in[10];
    const float* lin_b      = (const float*)d_in[11];
    const float* start_t    = (const float*)d_in[12];
    const float* end_t      = (const float*)d_in[13];
    const float* trans      = (const float*)d_in[14];
    const int*   sent       = (const int*)d_in[15];
    const int*   word       = (const int*)d_in[16];
    const int*   tag        = (const int*)d_in[17];
    const unsigned* mask    = (const unsigned*)d_in[18];
    float* out = (float*)d_out;

    static int smem_set = 0;
    if (!smem_set) {
        cudaFuncSetAttribute(lstm_kernel, cudaFuncAttributeMaxDynamicSharedMemorySize, LSTM_SMEM);
        cudaFuncSetAttribute(emission_kernel, cudaFuncAttributeMaxDynamicSharedMemorySize, EM_SMEM);
        smem_set = 1;
    }

    init_kernel<<<2, 256>>>();
    mask_convert_kernel<<<32, 256>>>(mask);
    pad_w_kernel<<<(N2 * FP + 255) / 256, 256>>>(w_ih_f, w_ih_r);
    embed_conv_kernel<<<2048, 128>>>(word_table, char_table, conv_w, conv_b, sent, word);
    gemm_gx_kernel<<<dim3(16, 64), 256>>>(b_f, b_r);
    lstm_kernel<<<128, 256, LSTM_SMEM>>>(w_hh_f, w_hh_r);
    emission_kernel<<<128, 256, EM_SMEM>>>(lin_w, lin_b);
    crf_kernel<<<64, 32>>>(tag, start_t, end_t, trans);
    sum_kernel<<<1, 32>>>(out);
}

// round 9
// speedup vs baseline: 1.4203x; 1.1077x over previous
#include <cuda_runtime.h>
#include <cuda_bf16.h>
#include <math.h>
#include <stdint.h>

// ---------------- problem constants ----------------
#define BB 64      // batch
#define SS 128     // seq len
#define LW 20      // chars per word
#define CE 30      // char emb
#define CC 30      // char conv channels
#define WE 300     // word emb
#define HH 256     // hidden
#define NCL 25     // num classes
#define FF 330     // feature = WE + CC
#define KPAD 384   // padded K for bf16 MMA (6 chunks of 64)
#define NROW 8192  // S*B token rows
#define N2 2048    // 2 dirs * 4H

// ---------------- packed f32x2 helpers ----------------
#define FMA2(d, a, b) asm("fma.rn.f32x2 %0, %1, %2, %0;" : "+l"(d) : "l"(a), "l"(b))

__device__ __forceinline__ float2 unpk(unsigned long long v) {
    float2 f;
    asm("mov.b64 {%0, %1}, %2;" : "=f"(f.x), "=f"(f.y) : "l"(v));
    return f;
}

// ---------------- mma.sync helpers (baseline PTX, works on sm_103) ----------
__device__ __forceinline__ uint32_t smem_u32(const void* p) {
    uint32_t a;
    asm("{ .reg .u64 t; cvta.to.shared.u64 t, %1; cvt.u32.u64 %0, t; }" : "=r"(a) : "l"(p));
    return a;
}
#define SWZ(o) ((o) ^ (((o) >> 3) & 0x70))

#define LDSM_X4(r0, r1, r2, r3, a) \
    asm volatile("ldmatrix.sync.aligned.m8n8.x4.shared.b16 {%0,%1,%2,%3}, [%4];" \
                 : "=r"(r0), "=r"(r1), "=r"(r2), "=r"(r3) : "r"(a))

#define MMA_BF16(c0, c1, c2, c3, a0, a1, a2, a3, b0, b1) \
    asm volatile("mma.sync.aligned.m16n8k16.row.col.f32.bf16.bf16.f32 " \
                 "{%0,%1,%2,%3}, {%4,%5,%6,%7}, {%8,%9}, {%0,%1,%2,%3};" \
                 : "+f"(c0), "+f"(c1), "+f"(c2), "+f"(c3) \
                 : "r"(a0), "r"(a1), "r"(a2), "r"(a3), "r"(b0), "r"(b1))

// ---------------- static device scratch ----------------
__device__ __align__(16) __nv_bfloat16 g_featH[(size_t)NROW * KPAD];  // hi
__device__ __align__(16) __nv_bfloat16 g_featL[(size_t)NROW * KPAD];  // lo residual
__device__ __align__(16) __nv_bfloat16 g_wH[(size_t)N2 * KPAD];       // hi
__device__ __align__(16) __nv_bfloat16 g_wL[(size_t)N2 * KPAD];       // lo residual
__device__ float g_gx[(size_t)NROW * N2];     // [(t*2048+col)*64 + b]
__device__ float g_hT[2 * 2 * BB * HH];       // [dir][parity][b][u]
__device__ float g_hseq[(size_t)NROW * 512];  // [(t*512+ug)*64 + b]
__device__ float g_em[(size_t)NROW * NCL];    // [(t*64+b)*25 + c]
__device__ int   g_mask[BB * SS];             // [b][t]
__device__ float g_nll[BB];
__device__ unsigned g_cnt[2][SS];             // per-step arrival counters

__device__ __forceinline__ float sigf(float x) { return 1.0f / (1.0f + __expf(-x)); }

__device__ __forceinline__ void split_bf16(float v, __nv_bfloat16& hi, __nv_bfloat16& lo) {
    hi = __float2bfloat16_rn(v);
    lo = __float2bfloat16_rn(v - __bfloat162float(hi));
}

// ---------------- init ----------------
__global__ void init_kernel() {
    int tid = blockIdx.x * blockDim.x + threadIdx.x;
    for (int i = tid; i < 2 * SS; i += blockDim.x * gridDim.x) ((unsigned*)g_cnt)[i] = 0u;
    for (int i = tid; i < 2 * 2 * BB * HH; i += blockDim.x * gridDim.x) g_hT[i] = 0.0f;
    if (tid < BB) g_nll[tid] = 0.0f;
}

// ---------------- mask dtype detect + convert ----------------
__global__ void mask_convert_kernel(const unsigned* __restrict__ m) {
    unsigned v0 = m[0];
    int mode;  // 0 = int32, 1 = bytes, 2 = float32
    if (v0 == 0x01010101u) mode = 1;
    else if (v0 == 0x3F800000u) mode = 2;
    else mode = 0;
    int tid = blockIdx.x * blockDim.x + threadIdx.x;
    if (tid >= BB * SS) return;
    int v;
    if (mode == 1) {
        const unsigned char* mb = (const unsigned char*)m;
        v = (mb[tid] != 0) ? 1 : 0;
    } else if (mode == 2) {
        const float* mf = (const float*)m;
        v = (mf[tid] != 0.0f) ? 1 : 0;
    } else {
        v = (m[tid] != 0u) ? 1 : 0;
    }
    g_mask[tid] = v;
}

// ---------------- pad w_ih into bf16 hi/lo [2048][384] ----------------
__global__ void pad_w_kernel(const float* __restrict__ w_ih_f,
                             const float* __restrict__ w_ih_r) {
    int idx = blockIdx.x * blockDim.x + threadIdx.x;
    if (idx >= N2 * KPAD) return;
    int r = idx / KPAD, k = idx - r * KPAD;
    float v = 0.0f;
    if (k < FF) v = (r < 1024) ? w_ih_f[r * FF + k] : w_ih_r[(r - 1024) * FF + k];
    __nv_bfloat16 hi, lo;
    split_bf16(v, hi, lo);
    g_wH[idx] = hi;
    g_wL[idx] = lo;
}

// ---------------- char CNN + embedding concat -> featH/L (bf16) -------------
__global__ __launch_bounds__(128) void embed_conv_kernel(
    const float* __restrict__ word_table, const float* __restrict__ char_table,
    const float* __restrict__ conv_w, const float* __restrict__ conv_b,
    const int* __restrict__ sent, const int* __restrict__ word) {
    __shared__ float wsm[CC * CE * 3];   // 2700
    __shared__ float psm[4][22 * 32];    // per-warp padded char emb [pos][ic(32)]
    __shared__ int   cids[4][LW];

    int tid = threadIdx.x, w = tid >> 5, lane = tid & 31;
    int tok = blockIdx.x * 4 + w;        // tok = b*128 + s
    int b = tok >> 7, s = tok & 127;
    int row = s * BB + b;

    for (int i = tid; i < CC * CE * 3; i += 128) wsm[i] = conv_w[i];
    float* pw = psm[w];
    for (int i = lane; i < 22 * 32; i += 32) pw[i] = 0.0f;
    if (lane < LW) cids[w][lane] = word[tok * LW + lane];
    __syncthreads();

    for (int pos = 0; pos < LW; pos++) {
        if (lane < CE) {
            int c = cids[w][pos];
            pw[(pos + 1) * 32 + lane] = (c == 0) ? 0.0f : char_table[c * CE + lane];
        }
    }

    // word embedding copy (fp32 -> bf16 hi/lo)
    int widx = sent[tok];
    __nv_bfloat16* frowH = g_featH + (size_t)row * KPAD;
    __nv_bfloat16* frowL = g_featL + (size_t)row * KPAD;
    {
        const float4* wt = (const float4*)(word_table + (size_t)widx * WE);
        for (int j = lane; j < 75; j += 32) {
            float4 v = wt[j];
            __nv_bfloat16 h0, l0, h1, l1, h2, l2, h3, l3;
            split_bf16(v.x, h0, l0); split_bf16(v.y, h1, l1);
            split_bf16(v.z, h2, l2); split_bf16(v.w, h3, l3);
            __nv_bfloat162 ph0; ph0.x = h0; ph0.y = h1;
            __nv_bfloat162 ph1; ph1.x = h2; ph1.y = h3;
            __nv_bfloat162 pl0; pl0.x = l0; pl0.y = l1;
            __nv_bfloat162 pl1; pl1.x = l2; pl1.y = l3;
            *(__nv_bfloat162*)(frowH + j * 4) = ph0;
            *(__nv_bfloat162*)(frowH + j * 4 + 2) = ph1;
            *(__nv_bfloat162*)(frowL + j * 4) = pl0;
            *(__nv_bfloat162*)(frowL + j * 4 + 2) = pl1;
        }
    }
    __syncwarp();

    // conv: lane oc, weights in regs, x broadcast
    int oc = (lane < CC) ? lane : 0;
    float wreg[3][32];
#pragma unroll
    for (int k = 0; k < 3; k++)
#pragma unroll
        for (int ic = 0; ic < 32; ic++)
            wreg[k][ic] = (ic < CC) ? wsm[oc * 90 + ic * 3 + k] : 0.0f;

    float m = -1e30f;
    for (int t = 0; t < LW; t++) {
        float asum = 0.0f;
#pragma unroll
        for (int k = 0; k < 3; k++) {
            const float4* xr = (const float4*)(pw + (t + k) * 32);
            float acc = 0.0f;
#pragma unroll
            for (int j = 0; j < 8; j++) {
                float4 x = xr[j];
                acc += x.x * wreg[k][j * 4 + 0] + x.y * wreg[k][j * 4 + 1]
                     + x.z * wreg[k][j * 4 + 2] + x.w * wreg[k][j * 4 + 3];
            }
            asum += acc;
        }
        m = fmaxf(m, asum);
    }
    if (lane < CC) {
        __nv_bfloat16 hi, lo;
        split_bf16(m + conv_b[lane], hi, lo);
        frowH[WE + lane] = hi;
        frowL[WE + lane] = lo;
    }
    if (lane < 27) {
        __nv_bfloat162 z; z.x = __float2bfloat16_rn(0.0f); z.y = z.x;
        *(__nv_bfloat162*)(frowH + FF + 2 * lane) = z;
        *(__nv_bfloat162*)(frowL + FF + 2 * lane) = z;
    }
}

// ---------------- gx GEMM via mma.sync bf16, split hi/lo 3-pass -------------
// CTA tile 128(m) x 128(n), 8 warps of 64x32. K chunks of 64 bf16, 6 chunks.
// smem mainloop: Ah 16KB | Bh 16KB | Al 16KB | Bl 16KB = 64KB (single buffer).
// Epilogue reuses smem: 8 warps x 64x34 f32 = 69632 B.
#define GX_SMEM 69632
__global__ __launch_bounds__(256) void gemm_gx_mma_kernel(const float* __restrict__ bf,
                                                          const float* __restrict__ br) {
    extern __shared__ char smem[];
    uint32_t sbase = smem_u32(smem);
    int tid = threadIdx.x;
    int wid = tid >> 5, lane = tid & 31;
    int bn = blockIdx.x * 128;
    int bm = blockIdx.y * 128;

    int warp_m = wid & 1, warp_n = wid >> 1;
    int m0w = warp_m * 64, n0w = warp_n * 32;
    int g = lane >> 3;
    int rowA_off = (lane & 7) + (g & 1) * 8;
    int kA_off = (g >> 1) * 8;
    int rowB_off = (lane & 7) + (g >> 1) * 8;
    int kB_off = (g & 1) * 8;

    float acc[4][4][4];
#pragma unroll
    for (int i = 0; i < 4; i++)
#pragma unroll
        for (int j = 0; j < 4; j++)
#pragma unroll
            for (int q = 0; q < 4; q++) acc[i][j][q] = 0.0f;

    // G2S staging: 1024 uint4 per 128x64 tile; srow 0..31 (+j*32), su 0..7
    int srow = tid >> 3, su = tid & 7;
    const uint4* Agh = (const uint4*)(g_featH + (size_t)(bm + srow) * KPAD) + su;
    const uint4* Agl = (const uint4*)(g_featL + (size_t)(bm + srow) * KPAD) + su;
    const uint4* Bgh = (const uint4*)(g_wH + (size_t)(bn + srow) * KPAD) + su;
    const uint4* Bgl = (const uint4*)(g_wL + (size_t)(bn + srow) * KPAD) + su;

#pragma unroll 1
    for (int kc = 0; kc < 6; kc++) {
        // chunk kc covers k in [kc*64, kc*64+64): offset = kc*8 uint4 (128 B)
        if (kc > 0) __syncthreads();  // protect smem reuse (WAR)
#pragma unroll
        for (int j = 0; j < 4; j++) {
            size_t goff = (size_t)kc * 8 + (size_t)j * 32 * 48;  // row stride 48 uint4
            uint32_t so = SWZ((srow + j * 32) * 128 + su * 16);
            *(uint4*)(smem + 0 + so)     = Agh[goff];
            *(uint4*)(smem + 16384 + so) = Bgh[goff];
            *(uint4*)(smem + 32768 + so) = Agl[goff];
            *(uint4*)(smem + 49152 + so) = Bgl[goff];
        }
        __syncthreads();

        uint32_t sAh = sbase, sBh = sbase + 16384, sAl = sbase + 32768, sBl = sbase + 49152;
#pragma unroll
        for (int ks = 0; ks < 4; ks++) {
            int k0 = ks * 16;
            uint32_t ah[4][4], al[4][4];
#pragma unroll
            for (int mt = 0; mt < 4; mt++) {
                int rowA = m0w + mt * 16 + rowA_off;
                uint32_t off = SWZ(rowA * 128 + (k0 + kA_off) * 2);
                LDSM_X4(ah[mt][0], ah[mt][1], ah[mt][2], ah[mt][3], sAh + off);
                LDSM_X4(al[mt][0], al[mt][1], al[mt][2], al[mt][3], sAl + off);
            }
            uint32_t bh[2][4], bl[2][4];
#pragma unroll
            for (int nt2 = 0; nt2 < 2; nt2++) {
                int rowB = n0w + nt2 * 16 + rowB_off;
                uint32_t off = SWZ(rowB * 128 + (k0 + kB_off) * 2);
                LDSM_X4(bh[nt2][0], bh[nt2][1], bh[nt2][2], bh[nt2][3], sBh + off);
                LDSM_X4(bl[nt2][0], bl[nt2][1], bl[nt2][2], bl[nt2][3], sBl + off);
            }
#pragma unroll
            for (int mt = 0; mt < 4; mt++) {
#pragma unroll
                for (int nt = 0; nt < 4; nt++) {
                    uint32_t bh0 = bh[nt >> 1][(nt & 1) * 2 + 0];
                    uint32_t bh1 = bh[nt >> 1][(nt & 1) * 2 + 1];
                    uint32_t bl0 = bl[nt >> 1][(nt & 1) * 2 + 0];
                    uint32_t bl1 = bl[nt >> 1][(nt & 1) * 2 + 1];
                    float* c = acc[mt][nt];
                    MMA_BF16(c[0], c[1], c[2], c[3],
                             ah[mt][0], ah[mt][1], ah[mt][2], ah[mt][3], bh0, bh1);
                    MMA_BF16(c[0], c[1], c[2], c[3],
                             ah[mt][0], ah[mt][1], ah[mt][2], ah[mt][3], bl0, bl1);
                    MMA_BF16(c[0], c[1], c[2], c[3],
                             al[mt][0], al[mt][1], al[mt][2], al[mt][3], bh0, bh1);
                }
            }
        }
    }
    __syncthreads();

    // ---------------- epilogue: per-warp smem stage then coalesced stores ----
    float* Ep = (float*)smem + wid * (64 * 34);
    int lr = lane >> 2, lc2 = (lane & 3) * 2;
#pragma unroll
    for (int mt = 0; mt < 4; mt++) {
#pragma unroll
        for (int nt = 0; nt < 4; nt++) {
            int r0 = mt * 16 + lr;
            int col = nt * 8 + lc2;
            *(float2*)&Ep[r0 * 34 + col] = make_float2(acc[mt][nt][0], acc[mt][nt][1]);
            *(float2*)&Ep[(r0 + 8) * 34 + col] = make_float2(acc[mt][nt][2], acc[mt][nt][3]);
        }
    }
    __syncwarp();

    int t = blockIdx.y * 2 + warp_m;
    int halfl = lane >> 4, b4 = lane & 15;
#pragma unroll
    for (int c = 0; c < 16; c++) {
        int n_local = c * 2 + halfl;
        int n = bn + n0w + n_local;
        float bias = (n < 1024) ? __ldg(&bf[n]) : __ldg(&br[n - 1024]);
        float4 v;
        v.x = Ep[(b4 * 4 + 0) * 34 + n_local] + bias;
        v.y = Ep[(b4 * 4 + 1) * 34 + n_local] + bias;
        v.z = Ep[(b4 * 4 + 2) * 34 + n_local] + bias;
        v.w = Ep[(b4 * 4 + 3) * 34 + n_local] + bias;
        *(float4*)&g_gx[((size_t)t * N2 + n) * 64 + b4 * 4] = v;
    }
}

// ---------------- per-direction, per-step arrival barrier ----------------
__device__ __forceinline__ void grid_barrier(int dir, int step) {
    __syncthreads();
    if (threadIdx.x == 0) {
        __threadfence();
        atomicAdd(&g_cnt[dir][step], 1u);
        volatile unsigned* c = &g_cnt[dir][step];
        while (*c < 64u) {}
    }
    __syncthreads();
}

// ---------------- persistent bidirectional LSTM ----------------
#define LSTM_SMEM ((16 * 260 + 64 * 260 + 16 * 68) * 4)
__global__ __launch_bounds__(256, 1) void lstm_kernel(const float* __restrict__ whh_f,
                                                      const float* __restrict__ whh_r) {
    extern __shared__ float sm[];
    float* Ws = sm;                          // [16][260]
    float* Hs = sm + 16 * 260;               // [64][260]
    float* Pre = sm + 16 * 260 + 64 * 260;   // [16][68]

    int dir = blockIdx.x >> 6;
    int u0 = (blockIdx.x & 63) * 4;
    const float* whh = dir ? whh_r : whh_f;
    int tid = threadIdx.x;

    int lane = tid & 31, w = tid >> 5;
    int r = lane & 15;
    int bh = lane >> 4;
    int bbase = w * 8 + bh * 4;
    int ab = tid & 63, au = tid >> 6;

    for (int i = tid; i < 16 * 256; i += 256) {
        int rr = i >> 8, k = i & 255;
        int g = rr >> 2, jj = rr & 3;
        Ws[rr * 260 + k] = whh[(size_t)(g * 256 + u0 + jj) * 256 + k];
    }

    float c = 0.0f;
    int p = 0;

    for (int step = 0; step < 128; step++) {
        int t = dir ? (127 - step) : step;

        size_t gxb = ((size_t)t * N2 + dir * 1024 + u0 + au) * 64 + ab;
        float ga0 = g_gx[gxb + 0 * 256 * 64];
        float ga1 = g_gx[gxb + 1 * 256 * 64];
        float ga2 = g_gx[gxb + 2 * 256 * 64];
        float ga3 = g_gx[gxb + 3 * 256 * 64];

        if (step) grid_barrier(dir, step);
        else __syncthreads();

        const float4* src = (const float4*)(g_hT + (size_t)(dir * 2 + p) * (BB * HH));
        for (int i = tid; i < 4096; i += 256) {
            float4 v = __ldcg(src + i);
            int e = i << 2;
            *(float4*)&Hs[(e >> 8) * 260 + (e & 255)] = v;
        }
        __syncthreads();

        {
            unsigned long long A0 = 0ull, A1 = 0ull, A2 = 0ull, A3 = 0ull;
            const float* wrow = Ws + r * 260;
            const float* h0 = Hs + (bbase + 0) * 260;
            const float* h1 = Hs + (bbase + 1) * 260;
            const float* h2 = Hs + (bbase + 2) * 260;
            const float* h3 = Hs + (bbase + 3) * 260;
#pragma unroll 8
            for (int k = 0; k < 256; k += 4) {
                ulonglong2 wv = *(const ulonglong2*)(wrow + k);
                ulonglong2 x0 = *(const ulonglong2*)(h0 + k);
                ulonglong2 x1 = *(const ulonglong2*)(h1 + k);
                ulonglong2 x2 = *(const ulonglong2*)(h2 + k);
                ulonglong2 x3 = *(const ulonglong2*)(h3 + k);
                FMA2(A0, wv.x, x0.x); FMA2(A0, wv.y, x0.y);
                FMA2(A1, wv.x, x1.x); FMA2(A1, wv.y, x1.y);
                FMA2(A2, wv.x, x2.x); FMA2(A2, wv.y, x2.y);
                FMA2(A3, wv.x, x3.x); FMA2(A3, wv.y, x3.y);
            }
            float2 f0 = unpk(A0), f1 = unpk(A1), f2 = unpk(A2), f3 = unpk(A3);
            Pre[r * 68 + bbase + 0] = f0.x + f0.y;
            Pre[r * 68 + bbase + 1] = f1.x + f1.y;
            Pre[r * 68 + bbase + 2] = f2.x + f2.y;
            Pre[r * 68 + bbase + 3] = f3.x + f3.y;
        }
        __syncthreads();

        float a0 = ga0 + Pre[(0 * 4 + au) * 68 + ab];
        float a1 = ga1 + Pre[(1 * 4 + au) * 68 + ab];
        float a2 = ga2 + Pre[(2 * 4 + au) * 68 + ab];
        float a3 = ga3 + Pre[(3 * 4 + au) * 68 + ab];

        float ig = sigf(a0), fg = sigf(a1), gg = tanhf(a2), og = sigf(a3);
        c = fg * c + ig * gg;
        float h = og * tanhf(c);

        int pn = p ^ 1;
        g_hT[(size_t)(dir * 2 + pn) * (BB * HH) + ab * 256 + (u0 + au)] = h;
        g_hseq[((size_t)t * 512 + dir * 256 + u0 + au) * 64 + ab] = h;
        p = pn;
    }
}

// ---------------- emission: em = h @ lin_w^T + lin_b ----------------
#define EM_SMEM (NCL * 512 * 4)
__global__ __launch_bounds__(256) void emission_kernel(const float* __restrict__ lin_w,
                                                       const float* __restrict__ lin_b) {
    extern __shared__ float EWs[];
    int t = blockIdx.x;
    int tid = threadIdx.x;
    for (int i = tid; i < NCL * 512; i += 256) EWs[i] = lin_w[i];
    __syncthreads();

    int b = tid & 63, cg = tid >> 6;
    float acc[7];
#pragma unroll
    for (int ci = 0; ci < 7; ci++) {
        int c0 = cg * 7 + ci;
        acc[ci] = (c0 < NCL) ? lin_b[c0] : 0.0f;
    }
    const float* hp = g_hseq + (size_t)t * 512 * 64 + b;
#pragma unroll 4
    for (int u = 0; u < 512; u++) {
        float hv = hp[(size_t)u * 64];
#pragma unroll
        for (int ci = 0; ci < 7; ci++) {
            int c0 = cg * 7 + ci;
            if (c0 < NCL) acc[ci] += hv * EWs[c0 * 512 + u];
        }
    }
#pragma unroll
    for (int ci = 0; ci < 7; ci++) {
        int c0 = cg * 7 + ci;
        if (c0 < NCL) g_em[((size_t)t * 64 + b) * NCL + c0] = acc[ci];
    }
}

// ---------------- CRF NLL (one block per batch, 1 warp) ----------------
__global__ __launch_bounds__(32) void crf_kernel(const int* __restrict__ tag,
                                                 const float* __restrict__ start_t,
                                                 const float* __restrict__ end_t,
                                                 const float* __restrict__ trans) {
    int b = blockIdx.x;
    int lane = threadIdx.x;

    __shared__ float tr[NCL * NCL];
    __shared__ float alphas[32];

    for (int i = lane; i < NCL * NCL; i += 32) tr[i] = trans[i];
    __syncwarp();

    float myscore = 0.0f;
    int mylen = 0;
    for (int t = lane; t < SS; t += 32) {
        int mk = g_mask[b * SS + t];
        mylen += mk;
        int tgt = tag[b * SS + t];
        if (t == 0) {
            myscore += start_t[tgt] + g_em[(size_t)b * NCL + tgt];
        } else if (mk) {
            int tgp = tag[b * SS + t - 1];
            myscore += tr[tgp * NCL + tgt] + g_em[((size_t)t * 64 + b) * NCL + tgt];
        }
    }
#pragma unroll
    for (int off = 16; off > 0; off >>= 1) {
        myscore += __shfl_xor_sync(0xFFFFFFFFu, myscore, off);
        mylen += __shfl_xor_sync(0xFFFFFFFFu, mylen, off);
    }
    float score = 0.0f;
    if (lane == 0) {
        int last = mylen - 1;
        score = myscore + end_t[tag[b * SS + last]];
    }

    if (lane < NCL) alphas[lane] = start_t[lane] + g_em[(size_t)b * NCL + lane];
    __syncwarp();

    for (int t = 1; t < SS; t++) {
        int mk = g_mask[b * SS + t];
        float nxt = 0.0f;
        if (lane < NCL) {
            float emv = g_em[((size_t)t * 64 + b) * NCL + lane];
            float m = -1e30f;
#pragma unroll
            for (int i = 0; i < NCL; i++) m = fmaxf(m, alphas[i] + tr[i * NCL + lane]);
            float s = 0.0f;
#pragma unroll
            for (int i = 0; i < NCL; i++) s += __expf(alphas[i] + tr[i * NCL + lane] - m);
            nxt = m + logf(s) + emv;
        }
        __syncwarp();
        if (lane < NCL && mk) alphas[lane] = nxt;
        __syncwarp();
    }

    float v = (lane < NCL) ? alphas[lane] + end_t[lane] : -1e30f;
    float m = v;
#pragma unroll
    for (int off = 16; off > 0; off >>= 1) m = fmaxf(m, __shfl_xor_sync(0xFFFFFFFFu, m, off));
    float s = __expf(v - m);
#pragma unroll
    for (int off = 16; off > 0; off >>= 1) s += __shfl_xor_sync(0xFFFFFFFFu, s, off);
    if (lane == 0) {
        float logZ = m + logf(s);
        g_nll[b] = -(score - logZ);
    }
}

// ---------------- deterministic final sum ----------------
__global__ void sum_kernel(float* out) {
    int lane = threadIdx.x;
    float s = g_nll[lane] + g_nll[lane + 32];
#pragma unroll
    for (int off = 16; off > 0; off >>= 1) s += __shfl_xor_sync(0xFFFFFFFFu, s, off);
    if (lane == 0) out[0] = s;
}

// ---------------- launch ----------------
extern "C" void kernel_launch(void* const* d_in, const int* in_sizes, int n_in,
                              void* d_out, int out_size) {
    const float* word_table = (const float*)d_in[0];
    const float* char_table = (const float*)d_in[1];
    const float* conv_w     = (const float*)d_in[2];
    const float* conv_b     = (const float*)d_in[3];
    const float* w_ih_f     = (const float*)d_in[4];
    const float* w_hh_f     = (const float*)d_in[5];
    const float* b_f        = (const float*)d_in[6];
    const float* w_ih_r     = (const float*)d_in[7];
    const float* w_hh_r     = (const float*)d_in[8];
    const float* b_r        = (const float*)d_in[9];
    const float* lin_w      = (const float*)d_in[10];
    const float* lin_b      = (const float*)d_in[11];
    const float* start_t    = (const float*)d_in[12];
    const float* end_t      = (const float*)d_in[13];
    const float* trans      = (const float*)d_in[14];
    const int*   sent       = (const int*)d_in[15];
    const int*   word       = (const int*)d_in[16];
    const int*   tag        = (const int*)d_in[17];
    const unsigned* mask    = (const unsigned*)d_in[18];
    float* out = (float*)d_out;

    static int smem_set = 0;
    if (!smem_set) {
        cudaFuncSetAttribute(lstm_kernel, cudaFuncAttributeMaxDynamicSharedMemorySize, LSTM_SMEM);
        cudaFuncSetAttribute(emission_kernel, cudaFuncAttributeMaxDynamicSharedMemorySize, EM_SMEM);
        cudaFuncSetAttribute(gemm_gx_mma_kernel, cudaFuncAttributeMaxDynamicSharedMemorySize, GX_SMEM);
        smem_set = 1;
    }

    init_kernel<<<2, 256>>>();
    mask_convert_kernel<<<32, 256>>>(mask);
    pad_w_kernel<<<(N2 * KPAD + 255) / 256, 256>>>(w_ih_f, w_ih_r);
    embed_conv_kernel<<<2048, 128>>>(word_table, char_table, conv_w, conv_b, sent, word);
    gemm_gx_mma_kernel<<<dim3(16, 64), 256, GX_SMEM>>>(b_f, b_r);
    lstm_kernel<<<128, 256, LSTM_SMEM>>>(w_hh_f, w_hh_r);
    emission_kernel<<<128, 256, EM_SMEM>>>(lin_w, lin_b);
    crf_kernel<<<64, 32>>>(tag, start_t, end_t, trans);
    sum_kernel<<<1, 32>>>(out);
}